// round 4
// baseline (speedup 1.0000x reference)
#include <cuda_runtime.h>
#include <cuda_bf16.h>

// VoxelCollisionCost: B=1024, H=32, L=8 links, S=8 spheres, 256^3 SDF grid.
// One thread handles TWO (b,h,l) units (ILP=2 -> 16 gathers in flight).
// 8 lanes (l fastest) share one (b,h) -> shfl_xor reduce over links.

#define GRID_N   256
#define N_LINKS  8
#define N_SPH    8
#define BH_PER_BLOCK 64   // 2 units x 32 bh-groups of 8 lanes

// L2 policy descriptors (cache-hint form; modifier form is illegal for
// scalar widths on sm_103).
__device__ __forceinline__ unsigned long long pol_evict_last() {
    unsigned long long p;
    asm("createpolicy.fractional.L2::evict_last.b64 %0, 1.0;" : "=l"(p));
    return p;
}
__device__ __forceinline__ unsigned long long pol_evict_first() {
    unsigned long long p;
    asm("createpolicy.fractional.L2::evict_first.b64 %0, 1.0;" : "=l"(p));
    return p;
}
// SDF gather: keep grid lines resident in L2 across replays.
__device__ __forceinline__ float ldg_sdf(const float* p, unsigned long long pol) {
    float v;
    asm volatile("ld.global.nc.L2::cache_hint.f32 %0, [%1], %2;"
                 : "=f"(v) : "l"(p), "l"(pol));
    return v;
}
// Streaming pose loads: use-once, don't evict the grid.
__device__ __forceinline__ float4 ldg_stream4(const float4* p, unsigned long long pol) {
    float4 v;
    asm volatile("ld.global.nc.L2::cache_hint.v4.f32 {%0,%1,%2,%3}, [%4], %5;"
                 : "=f"(v.x), "=f"(v.y), "=f"(v.z), "=f"(v.w) : "l"(p), "l"(pol));
    return v;
}

__global__ void __launch_bounds__(256) vox_cost_kernel(
    const float* __restrict__ link_pos,   // [B,H,8,3]
    const float* __restrict__ link_rot,   // [B,H,8,3,3]
    const float* __restrict__ sph_ctr,    // [8,8,3]
    const float* __restrict__ sph_rad,    // [8,8]
    const float* __restrict__ sdf,        // [256,256,256]
    const float* __restrict__ weight,     // [1]
    float* __restrict__ out)              // [B,H]
{
    __shared__ float s_ctr[N_LINKS * N_SPH * 3];   // 192
    __shared__ float s_rad[N_LINKS * N_SPH];       // 64
    // 64 bh-groups: pos 64*24=1536 floats, rot 64*72=4608 floats
    __shared__ float s_stage[6144];

    const int tid = threadIdx.x;
    const unsigned long long polL = pol_evict_last();
    const unsigned long long polF = pol_evict_first();

    // Robot model -> smem (256 floats, one per thread)
    if (tid < 192) s_ctr[tid] = sph_ctr[tid];
    else           s_rad[tid - 192] = sph_rad[tid - 192];

    // Stage this block's 64 (b,h) poses via float4 with evict_first.
    // pos: 384 float4 ; rot: 1152 float4 ; total 1536 float4 = 6 per thread.
    const float4* posv = reinterpret_cast<const float4*>(link_pos) + (size_t)blockIdx.x * 384;
    const float4* rotv = reinterpret_cast<const float4*>(link_rot) + (size_t)blockIdx.x * 1152;
    float4* s4 = reinterpret_cast<float4*>(s_stage);
    #pragma unroll
    for (int k = 0; k < 6; k++) {
        int j = tid + k * 256;
        s4[j] = (j < 384) ? ldg_stream4(posv + j, polF)
                          : ldg_stream4(rotv + (j - 384), polF);
    }
    __syncthreads();

    const int lbh = tid >> 3;      // local bh index for unit A: 0..31 (B: +32)
    const int l   = tid & 7;       // link index

    // Per-unit voxel index computation (exact reference semantics).
    int linA[N_SPH], linB[N_SPH];
    #pragma unroll
    for (int u = 0; u < 2; u++) {
        const int bh = lbh + u * 32;
        const float* R = s_stage + 1536 + bh * 72 + l * 9;
        const float* P = s_stage +        bh * 24 + l * 3;
        const float r00 = R[0], r01 = R[1], r02 = R[2];
        const float r10 = R[3], r11 = R[4], r12 = R[5];
        const float r20 = R[6], r21 = R[7], r22 = R[8];
        const float px = P[0], py = P[1], pz = P[2];
        int* lin = u ? linB : linA;
        #pragma unroll
        for (int s = 0; s < N_SPH; s++) {
            const float* c = s_ctr + (l * N_SPH + s) * 3;
            const float cx = c[0], cy = c[1], cz = c[2];
            const float x = fmaf(r00, cx, fmaf(r01, cy, fmaf(r02, cz, px)));
            const float y = fmaf(r10, cx, fmaf(r11, cy, fmaf(r12, cz, py)));
            const float z = fmaf(r20, cx, fmaf(r21, cy, fmaf(r22, cz, pz)));
            int ix = (int)floorf(__fdiv_rn(x + 1.28f, 0.01f));
            int iy = (int)floorf(__fdiv_rn(y + 1.28f, 0.01f));
            int iz = (int)floorf(__fdiv_rn(z + 1.28f, 0.01f));
            ix = min(max(ix, 0), GRID_N - 1);
            iy = min(max(iy, 0), GRID_N - 1);
            iz = min(max(iz, 0), GRID_N - 1);
            lin[s] = (ix << 16) | (iy << 8) | iz;
        }
    }

    // Issue all 16 gathers back-to-back (max MLP), then consume.
    float penA[N_SPH], penB[N_SPH];
    #pragma unroll
    for (int s = 0; s < N_SPH; s++) penA[s] = ldg_sdf(sdf + linA[s], polL);
    #pragma unroll
    for (int s = 0; s < N_SPH; s++) penB[s] = ldg_sdf(sdf + linB[s], polL);

    const float w = weight[0];

    float mA = s_rad[l * N_SPH + 0] - penA[0];
    float mB = s_rad[l * N_SPH + 0] - penB[0];
    #pragma unroll
    for (int s = 1; s < N_SPH; s++) {
        mA = fmaxf(mA, s_rad[l * N_SPH + s] - penA[s]);
        mB = fmaxf(mB, s_rad[l * N_SPH + s] - penB[s]);
    }

    // threshold + clip + /0.25 (== *4 exactly)
    float resA = fminf(fmaxf(mA - 0.01f, 0.0f), 0.5f) * 4.0f;
    float resB = fminf(fmaxf(mB - 0.01f, 0.0f), 0.5f) * 4.0f;

    // sum over 8 links (lanes l..l+7 share (b,h))
    #pragma unroll
    for (int d = 1; d <= 4; d <<= 1) {
        resA += __shfl_xor_sync(0xffffffffu, resA, d);
        resB += __shfl_xor_sync(0xffffffffu, resB, d);
    }

    if (l == 0) {
        const int base = blockIdx.x * BH_PER_BLOCK + lbh;
        out[base]      = w * resA;
        out[base + 32] = w * resB;
    }
}

extern "C" void kernel_launch(void* const* d_in, const int* in_sizes, int n_in,
                              void* d_out, int out_size) {
    const float* link_pos = (const float*)d_in[0];
    const float* link_rot = (const float*)d_in[1];
    const float* sph_ctr  = (const float*)d_in[2];
    const float* sph_rad  = (const float*)d_in[3];
    const float* sdf      = (const float*)d_in[4];
    const float* weight   = (const float*)d_in[5];
    float* out = (float*)d_out;

    const int n_bh   = out_size;                    // B*H = 32768
    const int blocks = n_bh / BH_PER_BLOCK;         // 512 blocks of 256 threads

    vox_cost_kernel<<<blocks, 256>>>(link_pos, link_rot, sph_ctr, sph_rad,
                                     sdf, weight, out);
}

// round 5
// speedup vs baseline: 1.1215x; 1.1215x over previous
#include <cuda_runtime.h>
#include <cuda_bf16.h>

// VoxelCollisionCost: B=1024, H=32, L=8 links, S=8 spheres, 256^3 SDF grid.
// One thread per (b,h,l); 8 lanes (l fastest) share one (b,h) -> shfl reduce.
// __launch_bounds__(256, 8) forces <=32 regs -> 8 blocks/SM -> the whole
// 1024-block grid is resident in ONE wave (no wave-quantization tail).

#define GRID_N   256
#define N_LINKS  8
#define N_SPH    8

__global__ void __launch_bounds__(256, 8) vox_cost_kernel(
    const float* __restrict__ link_pos,   // [B,H,8,3]
    const float* __restrict__ link_rot,   // [B,H,8,3,3]
    const float* __restrict__ sph_ctr,    // [8,8,3]
    const float* __restrict__ sph_rad,    // [8,8]
    const float* __restrict__ sdf,        // [256,256,256]
    const float* __restrict__ weight,     // [1]
    float* __restrict__ out)              // [B,H]
{
    __shared__ float s_ctr[N_LINKS * N_SPH * 3];   // 192
    __shared__ float s_rad[N_LINKS * N_SPH];       // 64
    __shared__ float s_stage[3072];                // 768 pos + 2304 rot floats

    const int tid = threadIdx.x;

    // Robot model -> smem (256 floats, one per thread)
    if (tid < 192) s_ctr[tid] = sph_ctr[tid];
    else           s_rad[tid - 192] = sph_rad[tid - 192];

    // Stage this block's 32 (b,h) poses via float4 (fully coalesced).
    // pos: 192 float4 ; rot: 576 float4 ; total 768 float4 = 3 per thread.
    const float4* posv = reinterpret_cast<const float4*>(link_pos) + (size_t)blockIdx.x * 192;
    const float4* rotv = reinterpret_cast<const float4*>(link_rot) + (size_t)blockIdx.x * 576;
    float4* s4 = reinterpret_cast<float4*>(s_stage);
    #pragma unroll
    for (int k = 0; k < 3; k++) {
        int j = tid + k * 256;
        s4[j] = (j < 192) ? __ldg(posv + j) : __ldg(rotv + (j - 192));
    }
    __syncthreads();

    const int lbh = tid >> 3;      // local (b,h) index within block: 0..31
    const int l   = tid & 7;       // link index

    // Conflict-free smem reads (bank map is a bijection across the warp).
    const float* R = s_stage + 768 + lbh * 72 + l * 9;
    const float* P = s_stage +       lbh * 24 + l * 3;
    const float r00 = R[0], r01 = R[1], r02 = R[2];
    const float r10 = R[3], r11 = R[4], r12 = R[5];
    const float r20 = R[6], r21 = R[7], r22 = R[8];
    const float px = P[0], py = P[1], pz = P[2];

    // Compute all 8 voxel indices (independent -> batched gathers).
    int lin[N_SPH];
    #pragma unroll
    for (int s = 0; s < N_SPH; s++) {
        const float* c = s_ctr + (l * N_SPH + s) * 3;
        const float cx = c[0], cy = c[1], cz = c[2];
        const float x = fmaf(r00, cx, fmaf(r01, cy, fmaf(r02, cz, px)));
        const float y = fmaf(r10, cx, fmaf(r11, cy, fmaf(r12, cz, py)));
        const float z = fmaf(r20, cx, fmaf(r21, cy, fmaf(r22, cz, pz)));
        // exact reference semantics: floor((p + 1.28) / 0.01) with rn-division
        int ix = (int)floorf(__fdiv_rn(x + 1.28f, 0.01f));
        int iy = (int)floorf(__fdiv_rn(y + 1.28f, 0.01f));
        int iz = (int)floorf(__fdiv_rn(z + 1.28f, 0.01f));
        ix = min(max(ix, 0), GRID_N - 1);
        iy = min(max(iy, 0), GRID_N - 1);
        iz = min(max(iz, 0), GRID_N - 1);
        lin[s] = (ix << 16) | (iy << 8) | iz;
    }

    // Gather + penetration depth; loads batch, subtracts retire as data lands.
    float pen[N_SPH];
    #pragma unroll
    for (int s = 0; s < N_SPH; s++)
        pen[s] = s_rad[l * N_SPH + s] - __ldg(sdf + lin[s]);

    float m = pen[0];
    #pragma unroll
    for (int s = 1; s < N_SPH; s++) m = fmaxf(m, pen[s]);

    // threshold + clip + /0.25 (== *4 exactly)
    float res = fminf(fmaxf(m - 0.01f, 0.0f), 0.5f) * 4.0f;

    // sum over 8 links (lanes l..l+7 share (b,h))
    res += __shfl_xor_sync(0xffffffffu, res, 1);
    res += __shfl_xor_sync(0xffffffffu, res, 2);
    res += __shfl_xor_sync(0xffffffffu, res, 4);

    if (l == 0)
        out[(blockIdx.x << 5) | lbh] = __ldg(weight) * res;
}

extern "C" void kernel_launch(void* const* d_in, const int* in_sizes, int n_in,
                              void* d_out, int out_size) {
    const float* link_pos = (const float*)d_in[0];
    const float* link_rot = (const float*)d_in[1];
    const float* sph_ctr  = (const float*)d_in[2];
    const float* sph_rad  = (const float*)d_in[3];
    const float* sdf      = (const float*)d_in[4];
    const float* weight   = (const float*)d_in[5];
    float* out = (float*)d_out;

    const int n_bh   = out_size;               // B*H = 32768
    const int blocks = (n_bh * N_LINKS) / 256; // 1024 blocks of 256 threads

    vox_cost_kernel<<<blocks, 256>>>(link_pos, link_rot, sph_ctr, sph_rad,
                                     sdf, weight, out);
}